// round 14
// baseline (speedup 1.0000x reference)
#include <cuda_runtime.h>

#define HH 50
#define TT 96
#define NPRED 12
#define NTH 64
#define EPB 2   // batch elements per block (per thread) — weights shared in registers

typedef unsigned long long u64;

__device__ __forceinline__ u64 pk2(float lo, float hi) {
    u64 r; asm("mov.b64 %0, {%1,%2};" : "=l"(r) : "f"(lo), "f"(hi)); return r;
}
__device__ __forceinline__ void upk2(u64 v, float &lo, float &hi) {
    asm("mov.b64 {%0,%1}, %2;" : "=f"(lo), "=f"(hi) : "l"(v));
}
__device__ __forceinline__ u64 ffma2(u64 a, u64 b, u64 c) {
    u64 d; asm("fma.rn.f32x2 %0, %1, %2, %3;" : "=l"(d) : "l"(a), "l"(b), "l"(c)); return d;
}
__device__ __forceinline__ float ftanh(float x) {
    float y; asm("tanh.approx.f32 %0, %1;" : "=f"(y) : "f"(x)); return y;
}
__device__ __forceinline__ float fsig(float x) {
    return fmaf(0.5f, ftanh(0.5f * x), 0.5f);
}

__global__ __launch_bounds__(NTH)
void lstm_recursive_kernel(const float* __restrict__ x,
                           const float* __restrict__ W_ih,
                           const float* __restrict__ W_hh,
                           const float* __restrict__ b_ih,
                           const float* __restrict__ b_hh,
                           const float* __restrict__ W_fc,
                           const float* __restrict__ b_fc,
                           float* __restrict__ out) {
    const int j  = threadIdx.x;                    // 0..63, ALL lanes active (branchless)
    const int jr = (j < HH) ? j : (HH - 1);        // clamped row: lanes 50-63 duplicate row 49
    const int b0 = blockIdx.x * EPB;

    // h buffers padded to 64: [0..49] real, [50..63] scratch written by clamped lanes
    __shared__ __align__(16) float sh[EPB][2][64];
    __shared__ float swin[EPB][TT + NPRED];
    __shared__ float sred[EPB][64];

#pragma unroll
    for (int e = 0; e < EPB; e++)
        for (int i = j; i < TT; i += NTH) swin[e][i] = x[(b0 + e) * TT + i];

    // thread owns gate rows jr, jr+50, jr+100, jr+150 (i,f,g,o) for BOTH elements
    u64 w[4][25];                    // 200 regs of packed W_hh K-pairs (shared across elements)
    float wih[4], bsum[4];
#pragma unroll
    for (int g = 0; g < 4; g++) {
        const int row = g * HH + jr;
        const float2* wr = (const float2*)(W_hh + row * HH);   // 8B aligned
#pragma unroll
        for (int k = 0; k < 25; k++) {
            float2 v = wr[k];
            w[g][k] = pk2(v.x, v.y);
        }
        wih[g]  = W_ih[row];
        bsum[g] = b_ih[row] + b_hh[row];
    }
    const float wfc = (j < HH) ? W_fc[jr] : 0.0f;   // zero so padded sred entries are 0
    const float bfc = b_fc[0];

    for (int p = 0; p < NPRED; p++) {
#pragma unroll
        for (int e = 0; e < EPB; e++) { sh[e][0][j] = 0.0f; sh[e][1][j] = 0.0f; }
        float cA = 0.0f, cB = 0.0f, hnA = 0.0f, hnB = 0.0f;
        __syncthreads();

#pragma unroll 1
        for (int t = 0; t < TT; t++) {
            const int buf = t & 1;
            const float xtA = swin[0][p + t];
            const float xtB = swin[1][p + t];

            // ---- prefetch ALL of A's h vectors (front-batched LDS, MLP) ----
            const ulonglong2* h0 = (const ulonglong2*)sh[0][buf];
            ulonglong2 hA[12];
#pragma unroll
            for (int cc = 0; cc < 12; cc++) hA[cc] = h0[cc];
            u64 htA = ((const u64*)sh[0][buf])[24];

            // ---- matvec A (4 chains) ----
            u64 a0, a1, a2, a3;
            a0 = pk2(fmaf(xtA, wih[0], bsum[0]), 0.0f);
            a1 = pk2(fmaf(xtA, wih[1], bsum[1]), 0.0f);
            a2 = pk2(fmaf(xtA, wih[2], bsum[2]), 0.0f);
            a3 = pk2(fmaf(xtA, wih[3], bsum[3]), 0.0f);
#pragma unroll
            for (int cc = 0; cc < 12; cc++) {
                a0 = ffma2(w[0][2 * cc], hA[cc].x, a0);
                a1 = ffma2(w[1][2 * cc], hA[cc].x, a1);
                a2 = ffma2(w[2][2 * cc], hA[cc].x, a2);
                a3 = ffma2(w[3][2 * cc], hA[cc].x, a3);
                a0 = ffma2(w[0][2 * cc + 1], hA[cc].y, a0);
                a1 = ffma2(w[1][2 * cc + 1], hA[cc].y, a1);
                a2 = ffma2(w[2][2 * cc + 1], hA[cc].y, a2);
                a3 = ffma2(w[3][2 * cc + 1], hA[cc].y, a3);
            }
            a0 = ffma2(w[0][24], htA, a0);
            a1 = ffma2(w[1][24], htA, a1);
            a2 = ffma2(w[2][24], htA, a2);
            a3 = ffma2(w[3][24], htA, a3);

            // ---- tail A (MUFU chain — should overlap matvec B's FFMA2 below) ----
            {
                float l0, hi0, l1, hi1, l2, hi2, l3, hi3;
                upk2(a0, l0, hi0);
                upk2(a1, l1, hi1);
                upk2(a2, l2, hi2);
                upk2(a3, l3, hi3);
                const float i_ = fsig(l0 + hi0);
                const float f_ = fsig(l1 + hi1);
                const float g_ = ftanh(l2 + hi2);
                const float o_ = fsig(l3 + hi3);
                cA  = fmaf(f_, cA, i_ * g_);
                hnA = o_ * ftanh(cA);
                sh[0][buf ^ 1][j] = hnA;
            }

            // ---- matvec B (independent of tail A; fills fma pipe during A's tanh) ----
            const ulonglong2* h1 = (const ulonglong2*)sh[1][buf];
            u64 b0r, b1r, b2r, b3r;
            b0r = pk2(fmaf(xtB, wih[0], bsum[0]), 0.0f);
            b1r = pk2(fmaf(xtB, wih[1], bsum[1]), 0.0f);
            b2r = pk2(fmaf(xtB, wih[2], bsum[2]), 0.0f);
            b3r = pk2(fmaf(xtB, wih[3], bsum[3]), 0.0f);
#pragma unroll
            for (int cc = 0; cc < 12; cc++) {
                ulonglong2 hv = h1[cc];
                b0r = ffma2(w[0][2 * cc], hv.x, b0r);
                b1r = ffma2(w[1][2 * cc], hv.x, b1r);
                b2r = ffma2(w[2][2 * cc], hv.x, b2r);
                b3r = ffma2(w[3][2 * cc], hv.x, b3r);
                b0r = ffma2(w[0][2 * cc + 1], hv.y, b0r);
                b1r = ffma2(w[1][2 * cc + 1], hv.y, b1r);
                b2r = ffma2(w[2][2 * cc + 1], hv.y, b2r);
                b3r = ffma2(w[3][2 * cc + 1], hv.y, b3r);
            }
            {
                u64 htB = ((const u64*)sh[1][buf])[24];
                b0r = ffma2(w[0][24], htB, b0r);
                b1r = ffma2(w[1][24], htB, b1r);
                b2r = ffma2(w[2][24], htB, b2r);
                b3r = ffma2(w[3][24], htB, b3r);
            }

            // ---- tail B ----
            {
                float l0, hi0, l1, hi1, l2, hi2, l3, hi3;
                upk2(b0r, l0, hi0);
                upk2(b1r, l1, hi1);
                upk2(b2r, l2, hi2);
                upk2(b3r, l3, hi3);
                const float i_ = fsig(l0 + hi0);
                const float f_ = fsig(l1 + hi1);
                const float g_ = ftanh(l2 + hi2);
                const float o_ = fsig(l3 + hi3);
                cB  = fmaf(f_, cB, i_ * g_);
                hnB = o_ * ftanh(cB);
                sh[1][buf ^ 1][j] = hnB;
            }
            __syncthreads();                       // new h visible for next step
        }

        // FC head: out = h . W_fc + b_fc  (wfc==0 for pad lanes -> sred pad entries are 0)
        sred[0][j] = hnA * wfc;
        sred[1][j] = hnB * wfc;
        __syncthreads();
        if (j < EPB) {
            float s = bfc;
#pragma unroll
            for (int k = 0; k < HH; k++) s += sred[j][k];
            swin[j][TT + p] = s;
            out[(b0 + j) * NPRED + p] = s;
        }
        __syncthreads();
    }
}

extern "C" void kernel_launch(void* const* d_in, const int* in_sizes, int n_in,
                              void* d_out, int out_size) {
    const float* x    = (const float*)d_in[0];
    const float* W_ih = (const float*)d_in[1];
    const float* W_hh = (const float*)d_in[2];
    const float* b_ih = (const float*)d_in[3];
    const float* b_hh = (const float*)d_in[4];
    const float* W_fc = (const float*)d_in[5];
    const float* b_fc = (const float*)d_in[6];
    float* out = (float*)d_out;

    const int B = out_size / NPRED;               // 1024
    lstm_recursive_kernel<<<B / EPB, NTH>>>(x, W_ih, W_hh, b_ih, b_hh, W_fc, b_fc, out);
}